// round 1
// baseline (speedup 1.0000x reference)
#include <cuda_runtime.h>

// Problem constants
#define BATCH 4
#define SEQ   2048
#define DMODEL 1024
#define EE    256      // per-scale embed
#define HH    4        // heads per scale
#define DKK   64       // head dim
#define NSC   4        // number of scales

// -------- static device scratch (allocation-free rule) --------
__device__ float g_Xs [BATCH * SEQ * EE];          // projected subsampled rows (max scale0)
__device__ float g_QKV[BATCH * SEQ * 3 * EE];      // qkv
__device__ float g_SC [(long long)BATCH * HH * SEQ * SEQ]; // scores/probs (max scale0) 268MB
__device__ float g_O  [BATCH * SEQ * EE];          // attention output (head-concat)
__device__ float g_Y  [(BATCH * (SEQ + SEQ/2 + SEQ/4 + SEQ/8)) * EE]; // per-scale outputs
__device__ float g_Z  [BATCH * SEQ * DMODEL];      // upsampled concat
__device__ float g_ZF [BATCH * SEQ * DMODEL];      // fusion GEMM output

// ---------------- generic tiled GEMM: C = A*B + bias ----------------
// A rows addressed via: off(r) = (r / rowsPerChunk)*chunkStride + (r % rowsPerChunk)*rowStride
// B is (K,N) row-major with ldB. C row-major ldC. M,N multiples of 64; K multiple of 16.
__global__ void gemm_bias_kernel(
    int M, int N, int K,
    const float* __restrict__ A, long long aRowStride, int aRowsPerChunk, long long aChunkStride,
    const float* __restrict__ B, int ldB,
    const float* __restrict__ bias,
    float* __restrict__ C, int ldC)
{
    __shared__ float As[16][65];   // [k][row]
    __shared__ float Bs[16][64];   // [k][col]
    const int tid = threadIdx.x;           // 256 threads
    const int tx = tid & 15, ty = tid >> 4;
    const int rowBase = blockIdx.y * 64;
    const int colBase = blockIdx.x * 64;

    float acc[4][4] = {};

    for (int k0 = 0; k0 < K; k0 += 16) {
        // load A tile 64x16 (1024 elems, 4 per thread)
        #pragma unroll
        for (int i = 0; i < 4; i++) {
            int idx = tid + i * 256;
            int r = idx >> 4;       // 0..63
            int c = idx & 15;       // 0..15
            int gr = rowBase + r;
            long long off = (long long)(gr / aRowsPerChunk) * aChunkStride
                          + (long long)(gr % aRowsPerChunk) * aRowStride + (k0 + c);
            As[c][r] = A[off];
        }
        // load B tile 16x64
        #pragma unroll
        for (int i = 0; i < 4; i++) {
            int idx = tid + i * 256;
            int r = idx >> 6;       // 0..15
            int c = idx & 63;       // 0..63
            Bs[r][c] = B[(long long)(k0 + r) * ldB + colBase + c];
        }
        __syncthreads();
        #pragma unroll
        for (int kk = 0; kk < 16; kk++) {
            float a[4], b[4];
            #pragma unroll
            for (int i = 0; i < 4; i++) a[i] = As[kk][ty * 4 + i];
            #pragma unroll
            for (int j = 0; j < 4; j++) b[j] = Bs[kk][tx * 4 + j];
            #pragma unroll
            for (int i = 0; i < 4; i++)
                #pragma unroll
                for (int j = 0; j < 4; j++)
                    acc[i][j] += a[i] * b[j];
        }
        __syncthreads();
    }
    #pragma unroll
    for (int i = 0; i < 4; i++) {
        int gr = rowBase + ty * 4 + i;
        #pragma unroll
        for (int j = 0; j < 4; j++) {
            int gc = colBase + tx * 4 + j;
            C[(long long)gr * ldC + gc] = acc[i][j] + bias[gc];
        }
    }
}

// ---------------- attention scores: S = Q K^T * scale ----------------
// grid: (L/64, L/64, B*H)
__global__ void attn_scores_kernel(int L, const float* __restrict__ qkv,
                                   float* __restrict__ scores, float scale)
{
    const int bh = blockIdx.z;
    const int b = bh / HH, h = bh % HH;
    const float* Qb = qkv + (long long)b * L * (3 * EE) + h * DKK;
    const float* Kb = Qb + EE;
    float* Cb = scores + (long long)bh * L * L;

    __shared__ float Qs[64][65];
    __shared__ float Ks[64][65];
    const int tid = threadIdx.x;
    const int qr0 = blockIdx.y * 64, kr0 = blockIdx.x * 64;

    #pragma unroll
    for (int i = 0; i < 16; i++) {
        int idx = tid + i * 256;
        int r = idx >> 6, c = idx & 63;
        Qs[r][c] = Qb[(long long)(qr0 + r) * (3 * EE) + c];
        Ks[r][c] = Kb[(long long)(kr0 + r) * (3 * EE) + c];
    }
    __syncthreads();

    const int tx = tid & 15, ty = tid >> 4;
    float acc[4][4] = {};
    #pragma unroll 8
    for (int d = 0; d < 64; d++) {
        float a[4], bb[4];
        #pragma unroll
        for (int i = 0; i < 4; i++) a[i] = Qs[ty * 4 + i][d];
        #pragma unroll
        for (int j = 0; j < 4; j++) bb[j] = Ks[tx * 4 + j][d];
        #pragma unroll
        for (int i = 0; i < 4; i++)
            #pragma unroll
            for (int j = 0; j < 4; j++)
                acc[i][j] += a[i] * bb[j];
    }
    #pragma unroll
    for (int i = 0; i < 4; i++) {
        int q = qr0 + ty * 4 + i;
        #pragma unroll
        for (int j = 0; j < 4; j++) {
            int k = kr0 + tx * 4 + j;
            Cb[(long long)q * L + k] = acc[i][j] * scale;
        }
    }
}

// ---------------- row softmax (in place). one block per row ----------------
__global__ void softmax_kernel(float* __restrict__ scores, int L)
{
    const long long row = blockIdx.x;
    float* p = scores + row * (long long)L;
    const int tid = threadIdx.x;
    const int per = L >> 8;               // L/256, 1..8
    float v[8];

    float m = -1e30f;
    #pragma unroll 8
    for (int i = 0; i < per; i++) { v[i] = p[tid + i * 256]; m = fmaxf(m, v[i]); }

    __shared__ float red[8];
    // block max
    #pragma unroll
    for (int o = 16; o; o >>= 1) m = fmaxf(m, __shfl_xor_sync(0xffffffffu, m, o));
    if ((tid & 31) == 0) red[tid >> 5] = m;
    __syncthreads();
    float mt = red[0];
    #pragma unroll
    for (int k = 1; k < 8; k++) mt = fmaxf(mt, red[k]);
    __syncthreads();

    float s = 0.f;
    #pragma unroll 8
    for (int i = 0; i < per; i++) { v[i] = __expf(v[i] - mt); s += v[i]; }
    #pragma unroll
    for (int o = 16; o; o >>= 1) s += __shfl_xor_sync(0xffffffffu, s, o);
    if ((tid & 31) == 0) red[tid >> 5] = s;
    __syncthreads();
    float st = 0.f;
    #pragma unroll
    for (int k = 0; k < 8; k++) st += red[k];
    const float inv = 1.f / st;
    #pragma unroll 8
    for (int i = 0; i < per; i++) p[tid + i * 256] = v[i] * inv;
}

// ---------------- w0 = mean over heads of scale-0 probs ----------------
__global__ void w0_mean_kernel(const float* __restrict__ probs, float* __restrict__ w0)
{
    const long long LL = (long long)SEQ * SEQ;
    long long idx = (long long)blockIdx.x * 256 + threadIdx.x;  // over B*S*S
    long long b = idx / LL;
    long long rem = idx - b * LL;
    const float* base = probs + b * HH * LL + rem;
    w0[idx] = 0.25f * (base[0] + base[LL] + base[2 * LL] + base[3 * LL]);
}

// ---------------- PV: O[.,h*64..] = P @ V ----------------
// grid: (1, L/64, B*H)
__global__ void attn_pv_kernel(int L, const float* __restrict__ probs,
                               const float* __restrict__ qkv, float* __restrict__ O)
{
    const int bh = blockIdx.z;
    const int b = bh / HH, h = bh % HH;
    const float* P = probs + (long long)bh * L * L;
    const float* V = qkv + (long long)b * L * (3 * EE) + 2 * EE + h * DKK;
    float* Cb = O + (long long)b * L * EE + h * DKK;
    const int row0 = blockIdx.y * 64;

    __shared__ float Ps[16][65];  // [k][row]
    __shared__ float Vs[16][64];  // [k][d]
    const int tid = threadIdx.x;
    const int tx = tid & 15, ty = tid >> 4;
    float acc[4][4] = {};

    for (int k0 = 0; k0 < L; k0 += 16) {
        #pragma unroll
        for (int i = 0; i < 4; i++) {
            int idx = tid + i * 256;
            int r = idx >> 4, c = idx & 15;
            Ps[c][r] = P[(long long)(row0 + r) * L + k0 + c];
        }
        #pragma unroll
        for (int i = 0; i < 4; i++) {
            int idx = tid + i * 256;
            int r = idx >> 6, c = idx & 63;
            Vs[r][c] = V[(long long)(k0 + r) * (3 * EE) + c];
        }
        __syncthreads();
        #pragma unroll
        for (int kk = 0; kk < 16; kk++) {
            float a[4], bb[4];
            #pragma unroll
            for (int i = 0; i < 4; i++) a[i] = Ps[kk][ty * 4 + i];
            #pragma unroll
            for (int j = 0; j < 4; j++) bb[j] = Vs[kk][tx * 4 + j];
            #pragma unroll
            for (int i = 0; i < 4; i++)
                #pragma unroll
                for (int j = 0; j < 4; j++)
                    acc[i][j] += a[i] * bb[j];
        }
        __syncthreads();
    }
    #pragma unroll
    for (int i = 0; i < 4; i++) {
        int r = row0 + ty * 4 + i;
        #pragma unroll
        for (int j = 0; j < 4; j++)
            Cb[(long long)r * EE + tx * 4 + j] = acc[i][j];
    }
}

// ---------------- upsample + concat into Z ----------------
__global__ void upsample_kernel(const float* __restrict__ Y, float* __restrict__ Z)
{
    long long idx = (long long)blockIdx.x * 256 + threadIdx.x;  // over B*S*DMODEL
    int c = (int)(idx & (DMODEL - 1));
    long long bt = idx >> 10;
    int t = (int)(bt & (SEQ - 1));
    int b = (int)(bt >> 11);
    int i = c >> 8;        // scale index
    int cc = c & 255;
    int L = SEQ >> i;
    int k = t >> i;
    int j = t & ((1 << i) - 1);
    float alpha = (float)j / (float)(1 << i);

    // row offsets of each scale inside g_Y
    const int yrowoff[4] = {0, BATCH * SEQ, BATCH * SEQ + BATCH * SEQ / 2,
                            BATCH * SEQ + BATCH * SEQ / 2 + BATCH * SEQ / 4};
    long long base = ((long long)yrowoff[i] + (long long)b * L + k) * EE + cc;
    float v = Y[base];
    float vn = (k + 1 < L) ? Y[base + EE] : 0.f;
    Z[idx] = (1.f - alpha) * v + alpha * vn;
}

// ---------------- layernorm rows of 1024 ----------------
__global__ void layernorm_kernel(const float* __restrict__ Zf,
                                 const float* __restrict__ gam, const float* __restrict__ bet,
                                 float* __restrict__ out)
{
    const long long row = blockIdx.x;
    const float* p = Zf + row * DMODEL;
    const int tid = threadIdx.x;
    float v[4];
    float s = 0.f, s2 = 0.f;
    #pragma unroll
    for (int i = 0; i < 4; i++) {
        v[i] = p[tid + i * 256];
        s += v[i]; s2 += v[i] * v[i];
    }
    __shared__ float rs[8], rs2[8];
    #pragma unroll
    for (int o = 16; o; o >>= 1) { s += __shfl_xor_sync(0xffffffffu, s, o);
                                   s2 += __shfl_xor_sync(0xffffffffu, s2, o); }
    if ((tid & 31) == 0) { rs[tid >> 5] = s; rs2[tid >> 5] = s2; }
    __syncthreads();
    float ts = 0.f, ts2 = 0.f;
    #pragma unroll
    for (int k = 0; k < 8; k++) { ts += rs[k]; ts2 += rs2[k]; }
    const float mu = ts * (1.f / DMODEL);
    const float var = ts2 * (1.f / DMODEL) - mu * mu;
    const float inv = rsqrtf(var + 1e-5f);
    #pragma unroll
    for (int i = 0; i < 4; i++) {
        int c = tid + i * 256;
        out[row * DMODEL + c] = (v[i] - mu) * inv * gam[c] + bet[c];
    }
}

// ---------------- launch ----------------
extern "C" void kernel_launch(void* const* d_in, const int* in_sizes, int n_in,
                              void* d_out, int out_size)
{
    (void)in_sizes; (void)n_in; (void)out_size;
    const float* x     = (const float*)d_in[0];
    const float* projW = (const float*)d_in[1];
    const float* projb = (const float*)d_in[2];
    const float* inW   = (const float*)d_in[3];
    const float* inb   = (const float*)d_in[4];
    const float* outW  = (const float*)d_in[5];
    const float* outb  = (const float*)d_in[6];
    const float* fusW  = (const float*)d_in[7];
    const float* fusb  = (const float*)d_in[8];
    const float* lng   = (const float*)d_in[9];
    const float* lnb   = (const float*)d_in[10];

    float* fused = (float*)d_out;
    float* w0 = fused + (long long)BATCH * SEQ * DMODEL;

    float *Xs, *QKV, *SC, *O, *Y, *Z, *ZF;
    cudaGetSymbolAddress((void**)&Xs,  g_Xs);
    cudaGetSymbolAddress((void**)&QKV, g_QKV);
    cudaGetSymbolAddress((void**)&SC,  g_SC);
    cudaGetSymbolAddress((void**)&O,   g_O);
    cudaGetSymbolAddress((void**)&Y,   g_Y);
    cudaGetSymbolAddress((void**)&Z,   g_Z);
    cudaGetSymbolAddress((void**)&ZF,  g_ZF);

    const dim3 blk(256);
    int yoff = 0;
    for (int i = 0; i < NSC; i++) {
        const int s = 1 << i;
        const int L = SEQ >> i;
        const int rows = BATCH * L;

        // projection of subsampled rows: (rows,1024)@(1024,256)
        gemm_bias_kernel<<<dim3(EE / 64, rows / 64), blk>>>(
            rows, EE, DMODEL,
            x, (long long)s * DMODEL, L, (long long)SEQ * DMODEL,
            projW + (long long)i * DMODEL * EE, EE,
            projb + i * EE, Xs, EE);

        // qkv: (rows,256)@(256,768)
        gemm_bias_kernel<<<dim3(3 * EE / 64, rows / 64), blk>>>(
            rows, 3 * EE, EE,
            Xs, (long long)EE, rows, 0LL,
            inW + (long long)i * EE * 3 * EE, 3 * EE,
            inb + i * 3 * EE, QKV, 3 * EE);

        // scores + softmax
        attn_scores_kernel<<<dim3(L / 64, L / 64, BATCH * HH), blk>>>(L, QKV, SC, 0.125f);
        softmax_kernel<<<BATCH * HH * L, blk>>>(SC, L);
        if (i == 0)
            w0_mean_kernel<<<(unsigned)(((long long)BATCH * SEQ * SEQ) / 256), blk>>>(SC, w0);

        // PV
        attn_pv_kernel<<<dim3(1, L / 64, BATCH * HH), blk>>>(L, SC, QKV, O);

        // out proj: (rows,256)@(256,256)
        gemm_bias_kernel<<<dim3(EE / 64, rows / 64), blk>>>(
            rows, EE, EE,
            O, (long long)EE, rows, 0LL,
            outW + (long long)i * EE * EE, EE,
            outb + i * EE, Y + (long long)yoff * EE, EE);

        yoff += rows;
    }

    // upsample + concat
    upsample_kernel<<<(unsigned)(((long long)BATCH * SEQ * DMODEL) / 256), blk>>>(Y, Z);

    // fusion GEMM: (8192,1024)@(1024,1024)
    gemm_bias_kernel<<<dim3(DMODEL / 64, (BATCH * SEQ) / 64), blk>>>(
        BATCH * SEQ, DMODEL, DMODEL,
        Z, (long long)DMODEL, BATCH * SEQ, 0LL,
        fusW, DMODEL, fusb, ZF, DMODEL);

    // layernorm -> fused output
    layernorm_kernel<<<BATCH * SEQ, blk>>>(ZF, lng, lnb, fused);
}